// round 12
// baseline (speedup 1.0000x reference)
#include <cuda_runtime.h>
#include <cstdint>

#define NPIXC   16384
#define PXB     16
#define THREADS 512

// persistent scratch: feats transposed into A-fragment order, tf32, 16 MB
__device__ uint32_t g_featsT[NPIXC * 256];

#define WSLICE  320                 // per-pixel per-stage words (16 m * 20)
#define WSTAGE  (16 * WSLICE)       // 5120
#define NSTG    4

// main-kernel smem word offsets
#define OFF_W    0                  // 4*5120 = 20480
#define OFF_W1F  20480              // 1536
#define OFF_B1   22016              // 64
#define OFF_W2F  22080              // 512
#define OFF_B2   22592              // 8
#define OFF_O    22600              // 128*17 = 2176
#define SMEM_WORDS 24776
#define SMEM_BYTES (SMEM_WORDS * 4)   // 99104 -> 2 blocks/SM (198KB < 228KB)

// transpose-kernel smem
#define TR_SMEM_WORDS (256 * 33)
#define TR_SMEM_BYTES (TR_SMEM_WORDS * 4)

__device__ __forceinline__ uint32_t cvt_tf32(float x) {
    uint32_t r;
    asm("cvt.rna.tf32.f32 %0, %1;" : "=r"(r) : "f"(x));
    return r;
}

__device__ __forceinline__ void mma_tf32(float* d, const uint32_t* a, uint32_t b0, uint32_t b1) {
    asm("mma.sync.aligned.m16n8k8.row.col.f32.tf32.tf32.f32 "
        "{%0,%1,%2,%3}, {%4,%5,%6,%7}, {%8,%9}, {%0,%1,%2,%3};"
        : "+f"(d[0]), "+f"(d[1]), "+f"(d[2]), "+f"(d[3])
        : "r"(a[0]), "r"(a[1]), "r"(a[2]), "r"(a[3]), "r"(b0), "r"(b1));
}

__device__ __forceinline__ void cp16(uint32_t dst, const void* src) {
    asm volatile("cp.async.cg.shared.global [%0], [%1], 16;" :: "r"(dst), "l"(src) : "memory");
}
__device__ __forceinline__ void cpcommit() {
    asm volatile("cp.async.commit_group;" ::: "memory");
}
template<int N> __device__ __forceinline__ void cpwait() {
    asm volatile("cp.async.wait_group %0;" :: "n"(N) : "memory");
}

// ---------------------------------------------------------------------------
// Kernel A: transpose feats [b][n][pix] -> featsT[pix][fragword], tf32
// ---------------------------------------------------------------------------
__global__ void __launch_bounds__(256)
tr_kernel(const float* __restrict__ y, const float* __restrict__ nz)
{
    extern __shared__ uint32_t ts[];
    const int tid  = threadIdx.x;
    const int lane = tid & 31;
    const int wid  = tid >> 5;
    const int p0   = blockIdx.x * 32;

    #pragma unroll 4
    for (int i = 0; i < 32; ++i) {
        int pl = wid * 32 + i;          // 0..255
        int b  = pl >> 4;
        int n  = pl & 15;
        const float* src = (n < 8) ? (y  + (size_t)(b * 8 + n)     * NPIXC)
                                   : (nz + (size_t)(b * 8 + n - 8) * NPIXC);
        float v = __ldg(src + p0 + lane);
        int t  = n >> 3, n7 = n & 7;
        int w  = t * 128 + ((b & 7) * 4 + (n7 >> 1)) * 4 + 2 * (n7 & 1) + (b >> 3);
        ts[w * 33 + lane] = cvt_tf32(v);
    }
    __syncthreads();

    const int px = tid >> 3;
    const int lo = (tid & 7) * 4;
    uint32_t* dst = g_featsT + (size_t)(p0 + px) * 256;
    #pragma unroll
    for (int sub = 0; sub < 8; ++sub) {
        int w = sub * 32 + lo;
        uint4 v = make_uint4(ts[(w + 0) * 33 + px], ts[(w + 1) * 33 + px],
                             ts[(w + 2) * 33 + px], ts[(w + 3) * 33 + px]);
        *(uint4*)(dst + w) = v;
    }
}

// ---------------------------------------------------------------------------
// Kernel B: barrier-free warp-per-pixel einsum (W via depth-4 cp.async) + MLP
// ---------------------------------------------------------------------------
__global__ void __launch_bounds__(THREADS, 2)
lr_kernel(const float* __restrict__ nz2,   // [16][NPIX][8]
          const float* __restrict__ wmap,  // [NPIX][9][16][16]
          const float* __restrict__ w1,    // [64][24]
          const float* __restrict__ b1,    // [64]
          const float* __restrict__ w2,    // [8][64]
          const float* __restrict__ b2,    // [8]
          const int*   __restrict__ nidx,  // [NPIX][9]
          float*       __restrict__ out)   // [16][8][NPIX]
{
    extern __shared__ uint32_t su[];
    float*    sW   = (float*)(su + OFF_W);
    uint32_t* sW1f = su + OFF_W1F;
    float*    sB1f = (float*)(su + OFF_B1);
    uint32_t* sW2f = su + OFF_W2F;
    float*    sB2f = (float*)(su + OFF_B2);
    float*    sOf  = (float*)(su + OFF_O);

    const int tid = threadIdx.x;
    const int p0  = blockIdx.x * PXB;
    const int l   = tid & 31;
    const int wid = tid >> 5;               // warp id == pixel
    const int p   = p0 + wid;

    // ---- W cp.async pipeline: warp-private px slice, 4 stages ----
    const float* wp4 = wmap + (size_t)p * 2304;
    const uint32_t wdst_px = (uint32_t)__cvta_generic_to_shared(sW) + (uint32_t)wid * WSLICE * 4;

    #define W_ISSUE(s_) do {                                                         \
        int s__ = (s_);                                                              \
        if (s__ < 9) {                                                               \
            const float4* wsrc = (const float4*)(wp4 + (size_t)s__ * 256);           \
            uint32_t wd = wdst_px + (uint32_t)(s__ & 3) * WSTAGE * 4;                \
            int j0 = l, j1 = l + 32;                                                 \
            cp16(wd + (((j0 >> 2) * 20 + (j0 & 3) * 4) << 2), wsrc + j0);            \
            cp16(wd + (((j1 >> 2) * 20 + (j1 & 3) * 4) << 2), wsrc + j1);            \
        }                                                                            \
        cpcommit();                                                                  \
    } while (0)

    W_ISSUE(0); W_ISSUE(1); W_ISSUE(2);

    // ---- small shared weights (fragment-ordered) ----
    for (int i = tid; i < 1536; i += THREADS) {          // w1^T B-frags [j8][kt3][l32][rg2]
        int j = i / 192, r = i - j * 192;
        int kt = r >> 6, r2 = r & 63, ll = r2 >> 1, rg = r2 & 1;
        int d = kt * 8 + (ll & 3) + rg * 4;
        int ii = j * 8 + (ll >> 2);
        sW1f[i] = cvt_tf32(w1[ii * 24 + d]);
    }
    if (tid < 512) {                                     // w2^T B-frags [kt8][l32][rg2]
        int i = tid;
        int kt = i >> 6, r2 = i & 63, ll = r2 >> 1, rg = r2 & 1;
        int row = kt * 8 + (ll & 3) + 4 * rg;
        int col = ll >> 2;
        sW2f[i] = cvt_tf32(w2[col * 64 + row]);
    }
    if (tid < 64)  sB1f[tid] = b1[tid];
    if (tid < 8)   sB2f[tid] = b2[tid];

    // ---- early loads: noise2 A-fragment for GEMM2 kt=2 ----
    float m2a0 = __ldg(nz2 + ((size_t)(l >> 2) * NPIXC + p) * 8 + (l & 3));
    float m2a1 = __ldg(nz2 + ((size_t)((l >> 2) + 8) * NPIXC + p) * 8 + (l & 3));
    float m2a2 = __ldg(nz2 + ((size_t)(l >> 2) * NPIXC + p) * 8 + (l & 3) + 4);
    float m2a3 = __ldg(nz2 + ((size_t)((l >> 2) + 8) * NPIXC + p) * 8 + (l & 3) + 4);

    // ---- neighbor indices ----
    int q[9];
    #pragma unroll
    for (int k = 0; k < 9; ++k) q[k] = __ldg(nidx + p * 9 + k);

    // ---- einsum: warp-private, barrier-free; A depth-1 regs, W depth-4 cp.async ----
    float d0[4] = {0.f, 0.f, 0.f, 0.f};
    float d1[4] = {0.f, 0.f, 0.f, 0.f};

    uint4 a0c = __ldg((const uint4*)(g_featsT + (size_t)q[0] * 256 + l * 4));
    uint4 a1c = __ldg((const uint4*)(g_featsT + (size_t)q[0] * 256 + 128 + l * 4));

    const int wo00 = (l >> 2) * 20 + 2 * (l & 3);        // m,   h0
    const int wo01 = (8 + (l >> 2)) * 20 + 2 * (l & 3);  // m+8, h0

    #pragma unroll
    for (int k = 0; k < 9; ++k) {
        uint4 a0n, a1n;
        if (k < 8) {
            a0n = __ldg((const uint4*)(g_featsT + (size_t)q[k + 1] * 256 + l * 4));
            a1n = __ldg((const uint4*)(g_featsT + (size_t)q[k + 1] * 256 + 128 + l * 4));
        }
        W_ISSUE(k + 3);
        cpwait<3>();
        __syncwarp();
        {
            const float* bb = sW + (k & 3) * WSTAGE + wid * WSLICE;
            float2 w00 = *(const float2*)(bb + wo00);
            float2 w01 = *(const float2*)(bb + wo01);
            float2 w10 = *(const float2*)(bb + wo00 + 8);
            float2 w11 = *(const float2*)(bb + wo01 + 8);
            uint32_t A0[4] = {a0c.x, a0c.y, a0c.z, a0c.w};
            mma_tf32(d0, A0, cvt_tf32(w00.x), cvt_tf32(w00.y));
            mma_tf32(d1, A0, cvt_tf32(w01.x), cvt_tf32(w01.y));
            uint32_t A1[4] = {a1c.x, a1c.y, a1c.z, a1c.w};
            mma_tf32(d0, A1, cvt_tf32(w10.x), cvt_tf32(w10.y));
            mma_tf32(d1, A1, cvt_tf32(w11.x), cvt_tf32(w11.y));
        }
        if (k < 8) { a0c = a0n; a1c = a1n; }
    }
    __syncthreads();   // sW1f/sW2f ready

    // ---- shuffle restage (validated R5..R11) ----
    const int srcA = (l & 28) | ((l & 3) >> 1);
    const int srcB = srcA + 2;
    const bool odd = (l & 1);

    #define RESTAGE(dd_, a_) do {                                                    \
        float x0 = __shfl_sync(0xffffffffu, (dd_)[0], srcA);                         \
        float x1 = __shfl_sync(0xffffffffu, (dd_)[1], srcA);                         \
        float x2 = __shfl_sync(0xffffffffu, (dd_)[2], srcA);                         \
        float x3 = __shfl_sync(0xffffffffu, (dd_)[3], srcA);                         \
        float y0 = __shfl_sync(0xffffffffu, (dd_)[0], srcB);                         \
        float y1 = __shfl_sync(0xffffffffu, (dd_)[1], srcB);                         \
        float y2 = __shfl_sync(0xffffffffu, (dd_)[2], srcB);                         \
        float y3 = __shfl_sync(0xffffffffu, (dd_)[3], srcB);                         \
        (a_)[0] = cvt_tf32(odd ? x1 : x0);                                           \
        (a_)[1] = cvt_tf32(odd ? x3 : x2);                                           \
        (a_)[2] = cvt_tf32(odd ? y1 : y0);                                           \
        (a_)[3] = cvt_tf32(odd ? y3 : y2);                                           \
    } while (0)

    // ---- GEMM2: H[16x64] = [D1 | noise2][16x24] * w1^T[24x64] ----
    float hh[8][4];
    #pragma unroll
    for (int j = 0; j < 8; ++j) { hh[j][0] = hh[j][1] = hh[j][2] = hh[j][3] = 0.f; }
    {
        uint32_t a[4];
        #pragma unroll
        for (int kt = 0; kt < 3; ++kt) {
            if (kt == 0)      RESTAGE(d0, a);
            else if (kt == 1) RESTAGE(d1, a);
            else {
                a[0] = cvt_tf32(m2a0); a[1] = cvt_tf32(m2a1);
                a[2] = cvt_tf32(m2a2); a[3] = cvt_tf32(m2a3);
            }
            #pragma unroll
            for (int j = 0; j < 8; ++j) {
                uint2 bf = *(const uint2*)(sW1f + (j * 3 + kt) * 64 + l * 2);
                mma_tf32(hh[j], a, bf.x, bf.y);
            }
        }
    }

    // bias + relu
    {
        int c0 = 2 * (l & 3);
        #pragma unroll
        for (int j = 0; j < 8; ++j) {
            float ba = sB1f[8 * j + c0], bb2 = sB1f[8 * j + c0 + 1];
            hh[j][0] = fmaxf(hh[j][0] + ba, 0.f);
            hh[j][1] = fmaxf(hh[j][1] + bb2, 0.f);
            hh[j][2] = fmaxf(hh[j][2] + ba, 0.f);
            hh[j][3] = fmaxf(hh[j][3] + bb2, 0.f);
        }
    }

    // ---- GEMM3: OUT[16x8] = H[16x64] * w2^T[64x8] ----
    float o[4] = {0.f, 0.f, 0.f, 0.f};
    {
        uint32_t a[4];
        #pragma unroll
        for (int j = 0; j < 8; ++j) {
            RESTAGE(hh[j], a);
            uint2 bf = *(const uint2*)(sW2f + j * 64 + l * 2);
            mma_tf32(o, a, bf.x, bf.y);
        }
    }
    {
        int f0  = 2 * (l & 3);
        int b0i = l >> 2;
        o[0] += sB2f[f0];
        o[1] += sB2f[f0 + 1];
        o[2] += sB2f[f0];
        o[3] += sB2f[f0 + 1];
        sOf[(b0i * 8 + f0) * 17 + wid]           = o[0];
        sOf[(b0i * 8 + f0 + 1) * 17 + wid]       = o[1];
        sOf[((b0i + 8) * 8 + f0) * 17 + wid]     = o[2];
        sOf[((b0i + 8) * 8 + f0 + 1) * 17 + wid] = o[3];
    }
    __syncthreads();

    // ---- coalesced output: out[bf][p0..p0+15] ----
    {
        int bf = tid >> 2;
        int c  = tid & 3;
        const float* rp = sOf + bf * 17 + c * 4;
        float4 v = make_float4(rp[0], rp[1], rp[2], rp[3]);
        *(float4*)(out + (size_t)bf * NPIXC + p0 + c * 4) = v;
    }
    #undef W_ISSUE
    #undef RESTAGE
}

extern "C" void kernel_launch(void* const* d_in, const int* in_sizes, int n_in,
                              void* d_out, int out_size)
{
    const float* y    = (const float*)d_in[0];
    const float* nz   = (const float*)d_in[1];
    const float* nz2  = (const float*)d_in[2];
    const float* wmap = (const float*)d_in[3];
    const float* w1   = (const float*)d_in[4];
    const float* b1   = (const float*)d_in[5];
    const float* w2   = (const float*)d_in[6];
    const float* b2   = (const float*)d_in[7];
    const int*   nidx = (const int*)d_in[8];
    float* out = (float*)d_out;

    cudaFuncSetAttribute(tr_kernel, cudaFuncAttributeMaxDynamicSharedMemorySize, TR_SMEM_BYTES);
    cudaFuncSetAttribute(lr_kernel, cudaFuncAttributeMaxDynamicSharedMemorySize, SMEM_BYTES);

    tr_kernel<<<NPIXC / 32, 256, TR_SMEM_BYTES>>>(y, nz);
    lr_kernel<<<NPIXC / PXB, THREADS, SMEM_BYTES>>>(nz2, wmap, w1, b1, w2, b2, nidx, out);
}

// round 13
// speedup vs baseline: 1.4418x; 1.4418x over previous
#include <cuda_runtime.h>
#include <cstdint>

#define NPIXC   16384
#define PXB     16
#define THREADS 512

// persistent scratch: feats transposed into A-fragment order, tf32, 16 MB
__device__ uint32_t g_featsT[NPIXC * 256];

// main-kernel smem word offsets
#define OFF_W1F  0                  // 1536
#define OFF_B1   1536               // 64
#define OFF_W2F  1600               // 512
#define OFF_B2   2112               // 8
#define OFF_O    2120               // 128*17 = 2176
#define SMEM_WORDS 4296
#define SMEM_BYTES (SMEM_WORDS * 4)   // 17184

// transpose-kernel smem: ts[w*33 + px]
#define TR_SMEM_WORDS (256 * 33)
#define TR_SMEM_BYTES (TR_SMEM_WORDS * 4)  // 33792

__device__ __forceinline__ uint32_t cvt_tf32(float x) {
    uint32_t r;
    asm("cvt.rna.tf32.f32 %0, %1;" : "=r"(r) : "f"(x));
    return r;
}

__device__ __forceinline__ void mma_tf32(float* d, const uint32_t* a, uint32_t b0, uint32_t b1) {
    asm("mma.sync.aligned.m16n8k8.row.col.f32.tf32.tf32.f32 "
        "{%0,%1,%2,%3}, {%4,%5,%6,%7}, {%8,%9}, {%0,%1,%2,%3};"
        : "+f"(d[0]), "+f"(d[1]), "+f"(d[2]), "+f"(d[3])
        : "r"(a[0]), "r"(a[1]), "r"(a[2]), "r"(a[3]), "r"(b0), "r"(b1));
}

// ---------------------------------------------------------------------------
// Kernel A: transpose feats [b][n][pix] -> featsT[pix][fragword], tf32
// fragword w for (b, n): t=n>>3, n7=n&7:
//   w = t*128 + ((b&7)*4 + (n7>>1))*4 + 2*(n7&1) + (b>>3)
// Read phase: 8 front-batched LDG.128 per thread (MLP=8).
// ---------------------------------------------------------------------------
__global__ void __launch_bounds__(256)
tr_kernel(const float* __restrict__ y, const float* __restrict__ nz)
{
    extern __shared__ uint32_t ts[];
    const int tid = threadIdx.x;
    const int p0  = blockIdx.x * 32;

    const int plane_lo = tid >> 3;        // 0..31 within a pass
    const int px0      = (tid & 7) * 4;   // 4-px group

    #pragma unroll
    for (int pass = 0; pass < 8; ++pass) {
        int pl = pass * 32 + plane_lo;    // 0..255
        int b  = pl >> 4;
        int n  = pl & 15;
        const float* src = (n < 8) ? (y  + (size_t)(b * 8 + n)     * NPIXC)
                                   : (nz + (size_t)(b * 8 + n - 8) * NPIXC);
        float4 v = __ldg((const float4*)(src + p0 + px0));
        int t  = n >> 3, n7 = n & 7;
        int w  = t * 128 + ((b & 7) * 4 + (n7 >> 1)) * 4 + 2 * (n7 & 1) + (b >> 3);
        ts[w * 33 + px0 + 0] = cvt_tf32(v.x);
        ts[w * 33 + px0 + 1] = cvt_tf32(v.y);
        ts[w * 33 + px0 + 2] = cvt_tf32(v.z);
        ts[w * 33 + px0 + 3] = cvt_tf32(v.w);
    }
    __syncthreads();

    // write phase: coalesced STG.128
    const int px = tid >> 3;
    const int lo = (tid & 7) * 4;
    uint32_t* dst = g_featsT + (size_t)(p0 + px) * 256;
    #pragma unroll
    for (int sub = 0; sub < 8; ++sub) {
        int w = sub * 32 + lo;
        uint4 v = make_uint4(ts[(w + 0) * 33 + px], ts[(w + 1) * 33 + px],
                             ts[(w + 2) * 33 + px], ts[(w + 3) * 33 + px]);
        *(uint4*)(dst + w) = v;
    }
}

// ---------------------------------------------------------------------------
// Kernel B: barrier-free warp-per-pixel einsum (W depth-2 reg pipeline) + MLP
// ---------------------------------------------------------------------------
__global__ void __launch_bounds__(THREADS, 2)
lr_kernel(const float* __restrict__ nz2,   // [16][NPIX][8]
          const float* __restrict__ wmap,  // [NPIX][9][16][16]
          const float* __restrict__ w1,    // [64][24]
          const float* __restrict__ b1,    // [64]
          const float* __restrict__ w2,    // [8][64]
          const float* __restrict__ b2,    // [8]
          const int*   __restrict__ nidx,  // [NPIX][9]
          float*       __restrict__ out)   // [16][8][NPIX]
{
    extern __shared__ uint32_t su[];
    uint32_t* sW1f = su + OFF_W1F;
    float*    sB1f = (float*)(su + OFF_B1);
    uint32_t* sW2f = su + OFF_W2F;
    float*    sB2f = (float*)(su + OFF_B2);
    float*    sOf  = (float*)(su + OFF_O);

    const int tid = threadIdx.x;
    const int p0  = blockIdx.x * PXB;
    const int l   = tid & 31;
    const int wid = tid >> 5;               // warp id == pixel
    const int p   = p0 + wid;

    // ---- small shared weights (fragment-ordered) ----
    for (int i = tid; i < 1536; i += THREADS) {          // w1^T B-frags [j8][kt3][l32][rg2]
        int j = i / 192, r = i - j * 192;
        int kt = r >> 6, r2 = r & 63, ll = r2 >> 1, rg = r2 & 1;
        int d = kt * 8 + (ll & 3) + rg * 4;
        int ii = j * 8 + (ll >> 2);
        sW1f[i] = cvt_tf32(w1[ii * 24 + d]);
    }
    if (tid < 512) {                                     // w2^T B-frags [kt8][l32][rg2]
        int i = tid;
        int kt = i >> 6, r2 = i & 63, ll = r2 >> 1, rg = r2 & 1;
        int row = kt * 8 + (ll & 3) + 4 * rg;
        int col = ll >> 2;
        sW2f[i] = cvt_tf32(w2[col * 64 + row]);
    }
    if (tid < 64)  sB1f[tid] = b1[tid];
    if (tid < 8)   sB2f[tid] = b2[tid];

    // ---- early loads: noise2 A-fragment for GEMM2 kt=2 ----
    float m2a0 = __ldg(nz2 + ((size_t)(l >> 2) * NPIXC + p) * 8 + (l & 3));
    float m2a1 = __ldg(nz2 + ((size_t)((l >> 2) + 8) * NPIXC + p) * 8 + (l & 3));
    float m2a2 = __ldg(nz2 + ((size_t)(l >> 2) * NPIXC + p) * 8 + (l & 3) + 4);
    float m2a3 = __ldg(nz2 + ((size_t)((l >> 2) + 8) * NPIXC + p) * 8 + (l & 3) + 4);

    // ---- neighbor indices ----
    int q[9];
    #pragma unroll
    for (int k = 0; k < 9; ++k) q[k] = __ldg(nidx + p * 9 + k);

    // ---- einsum: warp-private, barrier-free ----
    const float* wp = wmap + (size_t)p * 2304 + (l >> 2) * 16 + 2 * (l & 3);
    #define WLOAD(s_, r00, r01, r10, r11) do {                                       \
        const float* wt = wp + (s_) * 256;                                           \
        r00 = *(const float2*)(wt);                                                  \
        r01 = *(const float2*)(wt + 128);                                            \
        r10 = *(const float2*)(wt + 8);                                              \
        r11 = *(const float2*)(wt + 136);                                            \
    } while (0)

    float d0[4] = {0.f, 0.f, 0.f, 0.f};
    float d1[4] = {0.f, 0.f, 0.f, 0.f};

    uint4 a0c = __ldg((const uint4*)(g_featsT + (size_t)q[0] * 256 + l * 4));
    uint4 a1c = __ldg((const uint4*)(g_featsT + (size_t)q[0] * 256 + 128 + l * 4));

    // W depth-2 register double-buffer: wA holds even slices, wB odd.
    float2 wA0, wA1, wA2, wA3, wB0, wB1, wB2, wB3;
    WLOAD(0, wA0, wA1, wA2, wA3);
    WLOAD(1, wB0, wB1, wB2, wB3);

    #pragma unroll
    for (int k = 0; k < 9; ++k) {
        uint4 a0n, a1n;
        if (k < 8) {
            a0n = __ldg((const uint4*)(g_featsT + (size_t)q[k + 1] * 256 + l * 4));
            a1n = __ldg((const uint4*)(g_featsT + (size_t)q[k + 1] * 256 + 128 + l * 4));
        }
        {
            float2 u00, u01, u10, u11;
            if (k & 1) { u00 = wB0; u01 = wB1; u10 = wB2; u11 = wB3; }
            else       { u00 = wA0; u01 = wA1; u10 = wA2; u11 = wA3; }
            uint32_t A0[4] = {a0c.x, a0c.y, a0c.z, a0c.w};
            mma_tf32(d0, A0, cvt_tf32(u00.x), cvt_tf32(u00.y));
            mma_tf32(d1, A0, cvt_tf32(u01.x), cvt_tf32(u01.y));
            uint32_t A1[4] = {a1c.x, a1c.y, a1c.z, a1c.w};
            mma_tf32(d0, A1, cvt_tf32(u10.x), cvt_tf32(u10.y));
            mma_tf32(d1, A1, cvt_tf32(u11.x), cvt_tf32(u11.y));
        }
        // refill the just-consumed buffer with slice k+2 (2 iterations of cover)
        if (k < 7) {
            if (k & 1) WLOAD(k + 2, wB0, wB1, wB2, wB3);
            else       WLOAD(k + 2, wA0, wA1, wA2, wA3);
        }
        if (k < 8) { a0c = a0n; a1c = a1n; }
    }
    __syncthreads();   // sW1f/sW2f ready

    // ---- shuffle restage (validated R5..R11) ----
    const int srcA = (l & 28) | ((l & 3) >> 1);
    const int srcB = srcA + 2;
    const bool odd = (l & 1);

    #define RESTAGE(dd_, a_) do {                                                    \
        float x0 = __shfl_sync(0xffffffffu, (dd_)[0], srcA);                         \
        float x1 = __shfl_sync(0xffffffffu, (dd_)[1], srcA);                         \
        float x2 = __shfl_sync(0xffffffffu, (dd_)[2], srcA);                         \
        float x3 = __shfl_sync(0xffffffffu, (dd_)[3], srcA);                         \
        float y0 = __shfl_sync(0xffffffffu, (dd_)[0], srcB);                         \
        float y1 = __shfl_sync(0xffffffffu, (dd_)[1], srcB);                         \
        float y2 = __shfl_sync(0xffffffffu, (dd_)[2], srcB);                         \
        float y3 = __shfl_sync(0xffffffffu, (dd_)[3], srcB);                         \
        (a_)[0] = cvt_tf32(odd ? x1 : x0);                                           \
        (a_)[1] = cvt_tf32(odd ? x3 : x2);                                           \
        (a_)[2] = cvt_tf32(odd ? y1 : y0);                                           \
        (a_)[3] = cvt_tf32(odd ? y3 : y2);                                           \
    } while (0)

    // ---- GEMM2: H[16x64] = [D1 | noise2][16x24] * w1^T[24x64] ----
    float hh[8][4];
    #pragma unroll
    for (int j = 0; j < 8; ++j) { hh[j][0] = hh[j][1] = hh[j][2] = hh[j][3] = 0.f; }
    {
        uint32_t a[4];
        #pragma unroll
        for (int kt = 0; kt < 3; ++kt) {
            if (kt == 0)      RESTAGE(d0, a);
            else if (kt == 1) RESTAGE(d1, a);
            else {
                a[0] = cvt_tf32(m2a0); a[1] = cvt_tf32(m2a1);
                a[2] = cvt_tf32(m2a2); a[3] = cvt_tf32(m2a3);
            }
            #pragma unroll
            for (int j = 0; j < 8; ++j) {
                uint2 bf = *(const uint2*)(sW1f + (j * 3 + kt) * 64 + l * 2);
                mma_tf32(hh[j], a, bf.x, bf.y);
            }
        }
    }

    // bias + relu
    {
        int c0 = 2 * (l & 3);
        #pragma unroll
        for (int j = 0; j < 8; ++j) {
            float ba = sB1f[8 * j + c0], bb2 = sB1f[8 * j + c0 + 1];
            hh[j][0] = fmaxf(hh[j][0] + ba, 0.f);
            hh[j][1] = fmaxf(hh[j][1] + bb2, 0.f);
            hh[j][2] = fmaxf(hh[j][2] + ba, 0.f);
            hh[j][3] = fmaxf(hh[j][3] + bb2, 0.f);
        }
    }

    // ---- GEMM3: OUT[16x8] = H[16x64] * w2^T[64x8] ----
    float o[4] = {0.f, 0.f, 0.f, 0.f};
    {
        uint32_t a[4];
        #pragma unroll
        for (int j = 0; j < 8; ++j) {
            RESTAGE(hh[j], a);
            uint2 bf = *(const uint2*)(sW2f + j * 64 + l * 2);
            mma_tf32(o, a, bf.x, bf.y);
        }
    }
    {
        int f0  = 2 * (l & 3);
        int b0i = l >> 2;
        o[0] += sB2f[f0];
        o[1] += sB2f[f0 + 1];
        o[2] += sB2f[f0];
        o[3] += sB2f[f0 + 1];
        sOf[(b0i * 8 + f0) * 17 + wid]           = o[0];
        sOf[(b0i * 8 + f0 + 1) * 17 + wid]       = o[1];
        sOf[((b0i + 8) * 8 + f0) * 17 + wid]     = o[2];
        sOf[((b0i + 8) * 8 + f0 + 1) * 17 + wid] = o[3];
    }
    __syncthreads();

    // ---- coalesced output: out[bf][p0..p0+15] ----
    {
        int bf = tid >> 2;
        int c  = tid & 3;
        const float* rp = sOf + bf * 17 + c * 4;
        float4 v = make_float4(rp[0], rp[1], rp[2], rp[3]);
        *(float4*)(out + (size_t)bf * NPIXC + p0 + c * 4) = v;
    }
    #undef WLOAD
    #undef RESTAGE
}

extern "C" void kernel_launch(void* const* d_in, const int* in_sizes, int n_in,
                              void* d_out, int out_size)
{
    const float* y    = (const float*)d_in[0];
    const float* nz   = (const float*)d_in[1];
    const float* nz2  = (const float*)d_in[2];
    const float* wmap = (const float*)d_in[3];
    const float* w1   = (const float*)d_in[4];
    const float* b1   = (const float*)d_in[5];
    const float* w2   = (const float*)d_in[6];
    const float* b2   = (const float*)d_in[7];
    const int*   nidx = (const int*)d_in[8];
    float* out = (float*)d_out;

    cudaFuncSetAttribute(tr_kernel, cudaFuncAttributeMaxDynamicSharedMemorySize, TR_SMEM_BYTES);
    cudaFuncSetAttribute(lr_kernel, cudaFuncAttributeMaxDynamicSharedMemorySize, SMEM_BYTES);

    tr_kernel<<<NPIXC / 32, 256, TR_SMEM_BYTES>>>(y, nz);
    lr_kernel<<<NPIXC / PXB, THREADS, SMEM_BYTES>>>(nz2, wmap, w1, b1, w2, b2, nidx, out);
}

// round 14
// speedup vs baseline: 1.4958x; 1.0375x over previous
#include <cuda_runtime.h>
#include <cstdint>

#define NPIXC   16384
#define PXB     16
#define THREADS 512

// persistent scratch: feats transposed into A-fragment order, tf32, 16 MB
__device__ uint32_t g_featsT[NPIXC * 256];

// main-kernel smem word offsets
#define OFF_W1F  0                  // 1536
#define OFF_B1   1536               // 64
#define OFF_W2F  1600               // 512
#define OFF_B2   2112               // 8
#define OFF_O    2120               // 128*17 = 2176
#define SMEM_WORDS 4296
#define SMEM_BYTES (SMEM_WORDS * 4)   // 17184

// transpose-kernel smem: ts[w*33 + px]
#define TR_SMEM_WORDS (256 * 33)
#define TR_SMEM_BYTES (TR_SMEM_WORDS * 4)  // 33792

__device__ __forceinline__ uint32_t cvt_tf32(float x) {
    uint32_t r;
    asm("cvt.rna.tf32.f32 %0, %1;" : "=r"(r) : "f"(x));
    return r;
}

__device__ __forceinline__ void mma_tf32(float* d, const uint32_t* a, uint32_t b0, uint32_t b1) {
    asm("mma.sync.aligned.m16n8k8.row.col.f32.tf32.tf32.f32 "
        "{%0,%1,%2,%3}, {%4,%5,%6,%7}, {%8,%9}, {%0,%1,%2,%3};"
        : "+f"(d[0]), "+f"(d[1]), "+f"(d[2]), "+f"(d[3])
        : "r"(a[0]), "r"(a[1]), "r"(a[2]), "r"(a[3]), "r"(b0), "r"(b1));
}

// ---------------------------------------------------------------------------
// Kernel A: transpose feats [b][n][pix] -> featsT[pix][fragword], tf32
// NEW n-permutation (co-designed with float4 W loads):
//   feature n maps to tile t=(n>>1)&1, lane k-pos j=n>>2, reg r=n&1:
//   w = t*128 + ((b&7)*4 + (n>>2))*4 + 2*(n&1) + (b>>3)
// ---------------------------------------------------------------------------
__global__ void __launch_bounds__(256)
tr_kernel(const float* __restrict__ y, const float* __restrict__ nz)
{
    extern __shared__ uint32_t ts[];
    const int tid = threadIdx.x;
    const int p0  = blockIdx.x * 32;

    const int plane_lo = tid >> 3;        // 0..31 within a pass
    const int px0      = (tid & 7) * 4;   // 4-px group

    #pragma unroll
    for (int pass = 0; pass < 8; ++pass) {
        int pl = pass * 32 + plane_lo;    // 0..255
        int b  = pl >> 4;
        int n  = pl & 15;
        const float* src = (n < 8) ? (y  + (size_t)(b * 8 + n)     * NPIXC)
                                   : (nz + (size_t)(b * 8 + n - 8) * NPIXC);
        float4 v = __ldg((const float4*)(src + p0 + px0));
        int t = (n >> 1) & 1;
        int w = t * 128 + ((b & 7) * 4 + (n >> 2)) * 4 + 2 * (n & 1) + (b >> 3);
        ts[w * 33 + px0 + 0] = cvt_tf32(v.x);
        ts[w * 33 + px0 + 1] = cvt_tf32(v.y);
        ts[w * 33 + px0 + 2] = cvt_tf32(v.z);
        ts[w * 33 + px0 + 3] = cvt_tf32(v.w);
    }
    __syncthreads();

    // write phase: coalesced STG.128
    const int px = tid >> 3;
    const int lo = (tid & 7) * 4;
    uint32_t* dst = g_featsT + (size_t)(p0 + px) * 256;
    #pragma unroll
    for (int sub = 0; sub < 8; ++sub) {
        int w = sub * 32 + lo;
        uint4 v = make_uint4(ts[(w + 0) * 33 + px], ts[(w + 1) * 33 + px],
                             ts[(w + 2) * 33 + px], ts[(w + 3) * 33 + px]);
        *(uint4*)(dst + w) = v;
    }
}

// ---------------------------------------------------------------------------
// Kernel B: barrier-free warp-per-pixel einsum (W as 2x LDG.128/slice) + MLP
// ---------------------------------------------------------------------------
__global__ void __launch_bounds__(THREADS, 2)
lr_kernel(const float* __restrict__ nz2,   // [16][NPIX][8]
          const float* __restrict__ wmap,  // [NPIX][9][16][16]
          const float* __restrict__ w1,    // [64][24]
          const float* __restrict__ b1,    // [64]
          const float* __restrict__ w2,    // [8][64]
          const float* __restrict__ b2,    // [8]
          const int*   __restrict__ nidx,  // [NPIX][9]
          float*       __restrict__ out)   // [16][8][NPIX]
{
    extern __shared__ uint32_t su[];
    uint32_t* sW1f = su + OFF_W1F;
    float*    sB1f = (float*)(su + OFF_B1);
    uint32_t* sW2f = su + OFF_W2F;
    float*    sB2f = (float*)(su + OFF_B2);
    float*    sOf  = (float*)(su + OFF_O);

    const int tid = threadIdx.x;
    const int p0  = blockIdx.x * PXB;
    const int l   = tid & 31;
    const int wid = tid >> 5;               // warp id == pixel
    const int p   = p0 + wid;

    // ---- small shared weights (fragment-ordered) ----
    for (int i = tid; i < 1536; i += THREADS) {          // w1^T B-frags [j8][kt3][l32][rg2]
        int j = i / 192, r = i - j * 192;
        int kt = r >> 6, r2 = r & 63, ll = r2 >> 1, rg = r2 & 1;
        int d = kt * 8 + (ll & 3) + rg * 4;
        int ii = j * 8 + (ll >> 2);
        sW1f[i] = cvt_tf32(w1[ii * 24 + d]);
    }
    if (tid < 512) {                                     // w2^T B-frags [kt8][l32][rg2]
        int i = tid;
        int kt = i >> 6, r2 = i & 63, ll = r2 >> 1, rg = r2 & 1;
        int row = kt * 8 + (ll & 3) + 4 * rg;
        int col = ll >> 2;
        sW2f[i] = cvt_tf32(w2[col * 64 + row]);
    }
    if (tid < 64)  sB1f[tid] = b1[tid];
    if (tid < 8)   sB2f[tid] = b2[tid];

    // ---- early loads: noise2 A-fragment for GEMM2 kt=2 ----
    float m2a0 = __ldg(nz2 + ((size_t)(l >> 2) * NPIXC + p) * 8 + (l & 3));
    float m2a1 = __ldg(nz2 + ((size_t)((l >> 2) + 8) * NPIXC + p) * 8 + (l & 3));
    float m2a2 = __ldg(nz2 + ((size_t)(l >> 2) * NPIXC + p) * 8 + (l & 3) + 4);
    float m2a3 = __ldg(nz2 + ((size_t)((l >> 2) + 8) * NPIXC + p) * 8 + (l & 3) + 4);

    // ---- neighbor indices ----
    int q[9];
    #pragma unroll
    for (int k = 0; k < 9; ++k) q[k] = __ldg(nidx + p * 9 + k);

    // ---- einsum: warp-private, barrier-free ----
    // lane l reads W[m=(l>>2)][4*(l&3) .. 4*(l&3)+3] as ONE float4 (and m+8 at +128)
    const float* wp = wmap + (size_t)p * 2304 + (l >> 2) * 16 + 4 * (l & 3);
    #define WLOAD(s_, rA, rB) do {                                                   \
        const float* wt = wp + (s_) * 256;                                           \
        rA = *(const float4*)(wt);                                                   \
        rB = *(const float4*)(wt + 128);                                             \
    } while (0)

    float d0[4] = {0.f, 0.f, 0.f, 0.f};
    float d1[4] = {0.f, 0.f, 0.f, 0.f};

    uint4 a0c = __ldg((const uint4*)(g_featsT + (size_t)q[0] * 256 + l * 4));
    uint4 a1c = __ldg((const uint4*)(g_featsT + (size_t)q[0] * 256 + 128 + l * 4));

    // W depth-2 register double-buffer
    float4 wA0, wA1, wB0, wB1;
    WLOAD(0, wA0, wA1);
    WLOAD(1, wB0, wB1);

    #pragma unroll
    for (int k = 0; k < 9; ++k) {
        uint4 a0n, a1n;
        if (k < 8) {
            a0n = __ldg((const uint4*)(g_featsT + (size_t)q[k + 1] * 256 + l * 4));
            a1n = __ldg((const uint4*)(g_featsT + (size_t)q[k + 1] * 256 + 128 + l * 4));
        }
        {
            float4 uA, uB;
            if (k & 1) { uA = wB0; uB = wB1; }
            else       { uA = wA0; uB = wA1; }
            // tile0 (n = 4j, 4j+1): b = (uA.x, uA.y) rows m / (uB.x, uB.y) rows m+8
            uint32_t A0[4] = {a0c.x, a0c.y, a0c.z, a0c.w};
            mma_tf32(d0, A0, cvt_tf32(uA.x), cvt_tf32(uA.y));
            mma_tf32(d1, A0, cvt_tf32(uB.x), cvt_tf32(uB.y));
            // tile1 (n = 4j+2, 4j+3): b = (uA.z, uA.w) / (uB.z, uB.w)
            uint32_t A1[4] = {a1c.x, a1c.y, a1c.z, a1c.w};
            mma_tf32(d0, A1, cvt_tf32(uA.z), cvt_tf32(uA.w));
            mma_tf32(d1, A1, cvt_tf32(uB.z), cvt_tf32(uB.w));
        }
        // refill consumed buffer with slice k+2
        if (k < 7) {
            if (k & 1) WLOAD(k + 2, wB0, wB1);
            else       WLOAD(k + 2, wA0, wA1);
        }
        if (k < 8) { a0c = a0n; a1c = a1n; }
    }
    __syncthreads();   // sW1f/sW2f ready

    // ---- shuffle restage (validated R5..R13; d-frag layout unchanged) ----
    const int srcA = (l & 28) | ((l & 3) >> 1);
    const int srcB = srcA + 2;
    const bool odd = (l & 1);

    #define RESTAGE(dd_, a_) do {                                                    \
        float x0 = __shfl_sync(0xffffffffu, (dd_)[0], srcA);                         \
        float x1 = __shfl_sync(0xffffffffu, (dd_)[1], srcA);                         \
        float x2 = __shfl_sync(0xffffffffu, (dd_)[2], srcA);                         \
        float x3 = __shfl_sync(0xffffffffu, (dd_)[3], srcA);                         \
        float y0 = __shfl_sync(0xffffffffu, (dd_)[0], srcB);                         \
        float y1 = __shfl_sync(0xffffffffu, (dd_)[1], srcB);                         \
        float y2 = __shfl_sync(0xffffffffu, (dd_)[2], srcB);                         \
        float y3 = __shfl_sync(0xffffffffu, (dd_)[3], srcB);                         \
        (a_)[0] = cvt_tf32(odd ? x1 : x0);                                           \
        (a_)[1] = cvt_tf32(odd ? x3 : x2);                                           \
        (a_)[2] = cvt_tf32(odd ? y1 : y0);                                           \
        (a_)[3] = cvt_tf32(odd ? y3 : y2);                                           \
    } while (0)

    // ---- GEMM2: H[16x64] = [D1 | noise2][16x24] * w1^T[24x64] ----
    float hh[8][4];
    #pragma unroll
    for (int j = 0; j < 8; ++j) { hh[j][0] = hh[j][1] = hh[j][2] = hh[j][3] = 0.f; }
    {
        uint32_t a[4];
        #pragma unroll
        for (int kt = 0; kt < 3; ++kt) {
            if (kt == 0)      RESTAGE(d0, a);
            else if (kt == 1) RESTAGE(d1, a);
            else {
                a[0] = cvt_tf32(m2a0); a[1] = cvt_tf32(m2a1);
                a[2] = cvt_tf32(m2a2); a[3] = cvt_tf32(m2a3);
            }
            #pragma unroll
            for (int j = 0; j < 8; ++j) {
                uint2 bf = *(const uint2*)(sW1f + (j * 3 + kt) * 64 + l * 2);
                mma_tf32(hh[j], a, bf.x, bf.y);
            }
        }
    }

    // bias + relu
    {
        int c0 = 2 * (l & 3);
        #pragma unroll
        for (int j = 0; j < 8; ++j) {
            float ba = sB1f[8 * j + c0], bb2 = sB1f[8 * j + c0 + 1];
            hh[j][0] = fmaxf(hh[j][0] + ba, 0.f);
            hh[j][1] = fmaxf(hh[j][1] + bb2, 0.f);
            hh[j][2] = fmaxf(hh[j][2] + ba, 0.f);
            hh[j][3] = fmaxf(hh[j][3] + bb2, 0.f);
        }
    }

    // ---- GEMM3: OUT[16x8] = H[16x64] * w2^T[64x8] ----
    float o[4] = {0.f, 0.f, 0.f, 0.f};
    {
        uint32_t a[4];
        #pragma unroll
        for (int j = 0; j < 8; ++j) {
            RESTAGE(hh[j], a);
            uint2 bf = *(const uint2*)(sW2f + j * 64 + l * 2);
            mma_tf32(o, a, bf.x, bf.y);
        }
    }
    {
        int f0  = 2 * (l & 3);
        int b0i = l >> 2;
        o[0] += sB2f[f0];
        o[1] += sB2f[f0 + 1];
        o[2] += sB2f[f0];
        o[3] += sB2f[f0 + 1];
        sOf[(b0i * 8 + f0) * 17 + wid]           = o[0];
        sOf[(b0i * 8 + f0 + 1) * 17 + wid]       = o[1];
        sOf[((b0i + 8) * 8 + f0) * 17 + wid]     = o[2];
        sOf[((b0i + 8) * 8 + f0 + 1) * 17 + wid] = o[3];
    }
    __syncthreads();

    // ---- coalesced output: out[bf][p0..p0+15] ----
    {
        int bf = tid >> 2;
        int c  = tid & 3;
        const float* rp = sOf + bf * 17 + c * 4;
        float4 v = make_float4(rp[0], rp[1], rp[2], rp[3]);
        *(float4*)(out + (size_t)bf * NPIXC + p0 + c * 4) = v;
    }
    #undef WLOAD
    #undef RESTAGE
}

extern "C" void kernel_launch(void* const* d_in, const int* in_sizes, int n_in,
                              void* d_out, int out_size)
{
    const float* y    = (const float*)d_in[0];
    const float* nz   = (const float*)d_in[1];
    const float* nz2  = (const float*)d_in[2];
    const float* wmap = (const float*)d_in[3];
    const float* w1   = (const float*)d_in[4];
    const float* b1   = (const float*)d_in[5];
    const float* w2   = (const float*)d_in[6];
    const float* b2   = (const float*)d_in[7];
    const int*   nidx = (const int*)d_in[8];
    float* out = (float*)d_out;

    cudaFuncSetAttribute(tr_kernel, cudaFuncAttributeMaxDynamicSharedMemorySize, TR_SMEM_BYTES);
    cudaFuncSetAttribute(lr_kernel, cudaFuncAttributeMaxDynamicSharedMemorySize, SMEM_BYTES);

    tr_kernel<<<NPIXC / 32, 256, TR_SMEM_BYTES>>>(y, nz);
    lr_kernel<<<NPIXC / PXB, THREADS, SMEM_BYTES>>>(nz2, wmap, w1, b1, w2, b2, nidx, out);
}